// round 3
// baseline (speedup 1.0000x reference)
#include <cuda_runtime.h>
#include <cuda_bf16.h>

// FocalLoss: mean over [N,C,H,W] of  validf * class_weight * bce
//   class_weight = onehot ? A*(1-x)^2 : A*x^2   (RAW logits, per reference)
//   bce = max(x,0) - x*onehot + log1p(exp(-|x|))
// N=4, C=19, H=W=512.  Output: single float scalar.
// NOTE: JAX without x64 stores the "int64" labels as int32 on device.

#define NCLS 19
#define HW_SZ (512 * 512)          // 2^18
#define PIX_TOTAL (4 * 512 * 512)  // 2^20 pixels (N*H*W)
#define ALPHA_F 0.25f
#define TOTAL_ELEMS ((long long)4 * NCLS * 512 * 512)  // 19,922,944

__global__ void zero_out_kernel(float* out) {
    if (threadIdx.x == 0) out[0] = 0.0f;
}

__global__ __launch_bounds__(256) void focal_loss_kernel(
    const float* __restrict__ x,     // [N,C,H,W] logits
    const int*   __restrict__ label, // [N,H,W] int32
    float* __restrict__ out)         // scalar accumulator
{
    const int g  = blockIdx.x * blockDim.x + threadIdx.x;
    const int p4 = g * 4;  // base pixel of this thread's 4-pixel group
    float acc = 0.0f;

    if (p4 < PIX_TOTAL) {
        const int n  = p4 >> 18;           // pixel / HW
        const int hw = p4 & (HW_SZ - 1);   // pixel % HW

        // Load 4 int32 labels in one 16B load; reuse across all 19 channels.
        const int4 lv = *reinterpret_cast<const int4*>(label + p4);
        int L[4] = { lv.x, lv.y, lv.z, lv.w };
        float V[4];
        #pragma unroll
        for (int i = 0; i < 4; i++)
            V[i] = (L[i] >= 0 && L[i] != 255) ? 1.0f : 0.0f;

        const size_t base = (size_t)n * (NCLS * HW_SZ) + hw;

        #pragma unroll
        for (int c = 0; c < NCLS; c++) {
            float4 xv = *reinterpret_cast<const float4*>(x + base + (size_t)c * HW_SZ);
            float xs[4] = { xv.x, xv.y, xv.z, xv.w };
            #pragma unroll
            for (int i = 0; i < 4; i++) {
                const float xi = xs[i];
                const float t  = (V[i] != 0.0f && L[i] == c) ? 1.0f : 0.0f;
                // class weight from RAW logits
                const float wbase = (t == 1.0f) ? (1.0f - xi) : xi;
                const float cw = ALPHA_F * wbase * wbase;
                // numerically-stable BCE-with-logits
                const float bce = fmaxf(xi, 0.0f) - xi * t
                                + log1pf(__expf(-fabsf(xi)));
                acc += V[i] * bce * cw;
            }
        }
    }

    // Warp reduction
    #pragma unroll
    for (int o = 16; o > 0; o >>= 1)
        acc += __shfl_xor_sync(0xffffffffu, acc, o);

    __shared__ float warp_sums[8];  // 256 threads = 8 warps
    const int lane = threadIdx.x & 31;
    const int wid  = threadIdx.x >> 5;
    if (lane == 0) warp_sums[wid] = acc;
    __syncthreads();

    if (wid == 0) {
        float v = (lane < 8) ? warp_sums[lane] : 0.0f;
        #pragma unroll
        for (int o = 4; o > 0; o >>= 1)
            v += __shfl_xor_sync(0xffffffffu, v, o);
        if (lane == 0) {
            const float inv_total = 1.0f / (float)TOTAL_ELEMS;
            atomicAdd(out, v * inv_total);  // LOSS_WEIGHT = 1.0
        }
    }
}

extern "C" void kernel_launch(void* const* d_in, const int* in_sizes, int n_in,
                              void* d_out, int out_size) {
    const float* cls_score = (const float*)d_in[0];
    const int*   label     = (const int*)d_in[1];
    float* out = (float*)d_out;

    zero_out_kernel<<<1, 32>>>(out);

    const int groups  = PIX_TOTAL / 4;     // 262144 thread-groups
    const int threads = 256;
    const int blocks  = groups / threads;  // 1024 blocks
    focal_loss_kernel<<<blocks, threads>>>(cls_score, label, out);
}

// round 4
// speedup vs baseline: 1.9734x; 1.9734x over previous
#include <cuda_runtime.h>
#include <cuda_bf16.h>

// FocalLoss restructured:
//   per element (t=0 common case): f0(x) = x^2 * (relu(x) + sp(x)),  sp = log1p(exp(-|x|))
//   per pixel correction at label channel: f1(xL) - f0(xL),
//     f1(x) = (1-x)^2 * (relu(-x) + sp(x))        [since relu(x)-x = relu(-x)]
//   loss = ALPHA * mean over N*C*H*W of V * (sum_c f0 + corr)
// N=4, C=19, H=W=512. Labels stored as int32 (JAX default x32).

#define NCLS 19
#define HW_SZ (512 * 512)          // 2^18
#define PIX_TOTAL (4 * 512 * 512)  // 2^20 pixels
#define ALPHA_F 0.25f
#define TOTAL_ELEMS ((long long)4 * NCLS * 512 * 512)

__global__ void zero_out_kernel(float* out) {
    if (threadIdx.x == 0) out[0] = 0.0f;
}

__device__ __forceinline__ float softplus_neg_abs(float x) {
    // log1p(exp(-|x|)) via fast MUFU path; arg of log in (1,2], no cancellation.
    return __logf(1.0f + __expf(-fabsf(x)));
}

__global__ __launch_bounds__(256) void focal_loss_kernel(
    const float* __restrict__ x,     // [N,C,H,W]
    const int*   __restrict__ label, // [N,H,W] int32
    float* __restrict__ out)
{
    const int g  = blockIdx.x * blockDim.x + threadIdx.x;
    const int p4 = g * 4;
    float acc = 0.0f;

    if (p4 < PIX_TOTAL) {
        const int n  = p4 >> 18;
        const int hw = p4 & (HW_SZ - 1);

        const int4 lv = *reinterpret_cast<const int4*>(label + p4);
        int L[4] = { lv.x, lv.y, lv.z, lv.w };

        const size_t base = (size_t)n * (NCLS * HW_SZ) + hw;

        // ---- uniform t=0 sum: no label logic in the hot loop ----
        float S0[4] = {0.f, 0.f, 0.f, 0.f};
        #pragma unroll
        for (int c = 0; c < NCLS; c++) {
            const float4 xv = *reinterpret_cast<const float4*>(x + base + (size_t)c * HW_SZ);
            const float xs[4] = { xv.x, xv.y, xv.z, xv.w };
            #pragma unroll
            for (int i = 0; i < 4; i++) {
                const float xi = xs[i];
                const float p  = fmaxf(xi, 0.0f) + softplus_neg_abs(xi);
                S0[i] = fmaf(xi * xi, p, S0[i]);
            }
        }

        // ---- per-pixel correction at the label channel ----
        #pragma unroll
        for (int i = 0; i < 4; i++) {
            const bool valid = (L[i] >= 0 && L[i] != 255);
            const int  Ls    = valid ? L[i] : 0;                     // safe gather
            const float xl   = x[base + ((size_t)Ls << 18) + i];     // L1/L2 hit
            const float sp   = softplus_neg_abs(xl);
            const float omx  = 1.0f - xl;
            const float f1   = omx * omx * (fmaxf(-xl, 0.0f) + sp);  // t=1 term
            const float f0   = xl * xl * (fmaxf(xl, 0.0f) + sp);
            const float V    = valid ? 1.0f : 0.0f;
            acc = fmaf(V, S0[i] + (f1 - f0), acc);
        }
    }

    // Warp reduction
    #pragma unroll
    for (int o = 16; o > 0; o >>= 1)
        acc += __shfl_xor_sync(0xffffffffu, acc, o);

    __shared__ float warp_sums[8];
    const int lane = threadIdx.x & 31;
    const int wid  = threadIdx.x >> 5;
    if (lane == 0) warp_sums[wid] = acc;
    __syncthreads();

    if (wid == 0) {
        float v = (lane < 8) ? warp_sums[lane] : 0.0f;
        #pragma unroll
        for (int o = 4; o > 0; o >>= 1)
            v += __shfl_xor_sync(0xffffffffu, v, o);
        if (lane == 0) {
            const float scale = ALPHA_F / (float)TOTAL_ELEMS;  // LOSS_WEIGHT=1
            atomicAdd(out, v * scale);
        }
    }
}

extern "C" void kernel_launch(void* const* d_in, const int* in_sizes, int n_in,
                              void* d_out, int out_size) {
    const float* cls_score = (const float*)d_in[0];
    const int*   label     = (const int*)d_in[1];
    float* out = (float*)d_out;

    zero_out_kernel<<<1, 32>>>(out);

    const int groups  = PIX_TOTAL / 4;     // 262144
    const int threads = 256;
    const int blocks  = groups / threads;  // 1024
    focal_loss_kernel<<<blocks, threads>>>(cls_score, label, out);
}